// round 3
// baseline (speedup 1.0000x reference)
#include <cuda_runtime.h>
#include <cstdint>

typedef unsigned long long u64;

#define NQ   4
#define PROJ 64
#define TPB  256
#define WARPS (TPB/32)
#define GRID 592

// ---------------- f32x2 helpers (Blackwell packed fp32) ----------------
__device__ __forceinline__ u64 pk(float lo, float hi) {
    u64 r; asm("mov.b64 %0, {%1, %2};" : "=l"(r) : "f"(lo), "f"(hi)); return r;
}
__device__ __forceinline__ float2 upk(u64 v) {
    float2 r; asm("mov.b64 {%0, %1}, %2;" : "=f"(r.x), "=f"(r.y) : "l"(v)); return r;
}
__device__ __forceinline__ u64 fma2(u64 a, u64 b, u64 c) {
    u64 d; asm("fma.rn.f32x2 %0, %1, %2, %3;" : "=l"(d) : "l"(a), "l"(b), "l"(c)); return d;
}
__device__ __forceinline__ u64 mul2(u64 a, u64 b) {
    u64 d; asm("mul.rn.f32x2 %0, %1, %2;" : "=l"(d) : "l"(a), "l"(b)); return d;
}

// ---------------- device-global precomputed tables ----------------
// g_C[idx] for idx = ((e3*3+e2)*3+e1)*3+e0 : .x = (z0,z1) coeff, .y = (z2,z3) coeff
__device__ ulonglong2 g_C[81];
// 0..15: A = W^T W / 64, 16..19: u = W^T b / 64, 20: e=|b|^2/64,
// 21..24: wbar = colmean(W), 25: bbar = mean(b)
__device__ float g_consts[32];

// ---------------- Kernel A: build coefficient tensor and LN constants ----------------
__global__ void precompute_kernel(const float* __restrict__ weights,
                                  const float* __restrict__ W,
                                  const float* __restrict__ b)
{
    __shared__ float2 sM[8][4];
    __shared__ float sVr[16][16];   // [o][j]
    __shared__ float sVi[16][16];
    __shared__ u64 bufA[512];
    __shared__ u64 bufB[384];

    int tid = threadIdx.x;

    if (tid < 8) {
        int l = tid >> 2, w = tid & 3;
        float phi = weights[l * 12 + w * 3 + 0];
        float th  = weights[l * 12 + w * 3 + 1];
        float om  = weights[l * 12 + w * 3 + 2];
        float c, s; sincosf(0.5f * th, &s, &c);
        float ap = -0.5f * (phi + om);
        float am =  0.5f * (phi - om);
        float cap, sap, cam, sam;
        sincosf(ap, &sap, &cap);
        sincosf(am, &sam, &cam);
        sM[tid][0] = make_float2( c * cap,  c * sap);
        sM[tid][1] = make_float2(-s * cam, -s * sam);
        sM[tid][2] = make_float2( s * cam, -s * sam);
        sM[tid][3] = make_float2( c * cap, -c * sap);
    }
    __syncthreads();

    // V columns (16 threads) — V = U_ent * diag((-i)^popcount)
    if (tid < 16) {
        const int j = tid;
        float ar[16], ai[16];
        #pragma unroll
        for (int o = 0; o < 16; o++) { ar[o] = (o == j) ? 1.f : 0.f; ai[o] = 0.f; }
        #pragma unroll
        for (int l = 0; l < 2; l++) {
            #pragma unroll
            for (int w = 0; w < NQ; w++) {
                int g = l * 4 + w;
                float2 M00 = sM[g][0], M01 = sM[g][1], M10 = sM[g][2], M11 = sM[g][3];
                int mask = 8 >> w;
                #pragma unroll
                for (int k = 0; k < 16; k++) if (!(k & mask)) {
                    int k1 = k | mask;
                    float a0r = ar[k],  a0i = ai[k];
                    float a1r = ar[k1], a1i = ai[k1];
                    ar[k]  = M00.x*a0r - M00.y*a0i + M01.x*a1r - M01.y*a1i;
                    ai[k]  = M00.x*a0i + M00.y*a0r + M01.x*a1i + M01.y*a1r;
                    ar[k1] = M10.x*a0r - M10.y*a0i + M11.x*a1r - M11.y*a1i;
                    ai[k1] = M10.x*a0i + M10.y*a0r + M11.x*a1i + M11.y*a1r;
                }
            }
            int rr = (l % 3) + 1;
            #pragma unroll
            for (int w = 0; w < NQ; w++) {
                int cm = 8 >> w, tm = 8 >> ((w + rr) & 3);
                #pragma unroll
                for (int k = 0; k < 16; k++) if ((k & cm) && !(k & tm)) {
                    int k1 = k | tm;
                    float tr = ar[k], ti = ai[k];
                    ar[k] = ar[k1];  ai[k] = ai[k1];
                    ar[k1] = tr;     ai[k1] = ti;
                }
            }
        }
        int pc = __popc(j) & 3;
        float fr = (pc == 0) ? 1.f : ((pc == 2) ? -1.f : 0.f);
        float fi = (pc == 1) ? -1.f : ((pc == 3) ? 1.f : 0.f);
        #pragma unroll
        for (int o = 0; o < 16; o++) {
            sVr[o][j] = ar[o] * fr - ai[o] * fi;
            sVi[o][j] = ar[o] * fi + ai[o] * fr;
        }
    }

    // warp 1: projection / LN constants (independent of V)
    if (tid >= 32 && tid < 64) {
        int lane = tid - 32;
        float A[16], u4[4], wb[4], e = 0.f, bb = 0.f;
        #pragma unroll
        for (int i = 0; i < 16; i++) A[i] = 0.f;
        #pragma unroll
        for (int i = 0; i < 4; i++) { u4[i] = 0.f; wb[i] = 0.f; }
        #pragma unroll
        for (int rep = 0; rep < 2; rep++) {
            int r = lane + rep * 32;
            float4 wr = *(const float4*)(W + r * 4);
            float br = b[r];
            float wv[4] = {wr.x, wr.y, wr.z, wr.w};
            #pragma unroll
            for (int i = 0; i < 4; i++) {
                #pragma unroll
                for (int jj = 0; jj < 4; jj++) A[i * 4 + jj] += wv[i] * wv[jj];
                u4[i] += wv[i] * br;
                wb[i] += wv[i];
            }
            e += br * br; bb += br;
        }
        #pragma unroll
        for (int off = 16; off > 0; off >>= 1) {
            #pragma unroll
            for (int i = 0; i < 16; i++) A[i] += __shfl_xor_sync(0xffffffffu, A[i], off);
            #pragma unroll
            for (int i = 0; i < 4; i++) {
                u4[i] += __shfl_xor_sync(0xffffffffu, u4[i], off);
                wb[i] += __shfl_xor_sync(0xffffffffu, wb[i], off);
            }
            e  += __shfl_xor_sync(0xffffffffu, e, off);
            bb += __shfl_xor_sync(0xffffffffu, bb, off);
        }
        if (lane == 0) {
            const float inv = 1.f / 64.f;
            #pragma unroll
            for (int i = 0; i < 16; i++) g_consts[i] = A[i] * inv;
            #pragma unroll
            for (int i = 0; i < 4; i++) {
                g_consts[16 + i] = u4[i] * inv;
                g_consts[21 + i] = wb[i] * inv;
            }
            g_consts[20] = e * inv;
            g_consts[25] = bb * inv;
        }
    }
    __syncthreads();

    // S_w[j][k] = sum_o sign_w(o) (VR[o][j]VR[o][k] + VI[o][j]VI[o][k]),
    // scattered into pair-radix layout: p_w = 2*bit_w(j) + bit_w(k)
    {
        int j = tid >> 4, k = tid & 15;
        float a0 = 0.f, a1 = 0.f, a2 = 0.f, a3 = 0.f;
        #pragma unroll
        for (int o = 0; o < 16; o++) {
            float d = sVr[o][j] * sVr[o][k] + sVi[o][j] * sVi[o][k];
            a0 += (o & 8) ? -d : d;
            a1 += (o & 4) ? -d : d;
            a2 += (o & 2) ? -d : d;
            a3 += (o & 1) ? -d : d;
        }
        int p0 = 2 * ((j >> 3) & 1) + ((k >> 3) & 1);
        int p1 = 2 * ((j >> 2) & 1) + ((k >> 2) & 1);
        int p2 = 2 * ((j >> 1) & 1) + ((k >> 1) & 1);
        int p3 = 2 * (j & 1) + (k & 1);
        int idx = ((p0 * 4 + p1) * 4 + p2) * 4 + p3;
        bufA[idx * 2 + 0] = pk(a0, a1);
        bufA[idx * 2 + 1] = pk(a2, a3);
    }
    __syncthreads();

    // 4 per-wire contractions: pair index (radix 4) -> (1,cos,sin) basis (radix 3)
    // T: e=0 coeff = .5*(in00+in11); e=1 = .5*(in00-in11); e=2 = .5*(in01+in10)
    {
        const int pow3[4] = {1, 3, 9, 27};
        const int P4s[4]  = {64, 16, 4, 1};
        for (int s = 0; s < 4; s++) {
            u64* In  = (s & 1) ? bufB : bufA;
            u64* Out = (s & 1) ? bufA : bufB;
            int P4 = P4s[s];
            int nitems = pow3[s] * P4 * 2;
            if (tid < nitems) {
                int pack = tid & 1, i = tid >> 1;
                int E = i / P4, P = i % P4;
                float2 v0 = upk(In[((E * 4 + 0) * P4 + P) * 2 + pack]);
                float2 v1 = upk(In[((E * 4 + 1) * P4 + P) * 2 + pack]);
                float2 v2 = upk(In[((E * 4 + 2) * P4 + P) * 2 + pack]);
                float2 v3 = upk(In[((E * 4 + 3) * P4 + P) * 2 + pack]);
                Out[((E * 3 + 0) * P4 + P) * 2 + pack] = pk(0.5f*(v0.x+v3.x), 0.5f*(v0.y+v3.y));
                Out[((E * 3 + 1) * P4 + P) * 2 + pack] = pk(0.5f*(v0.x-v3.x), 0.5f*(v0.y-v3.y));
                Out[((E * 3 + 2) * P4 + P) * 2 + pack] = pk(0.5f*(v1.x+v2.x), 0.5f*(v1.y+v2.y));
            }
            __syncthreads();
        }
    }
    // result in bufA, layout ((e0*3+e1)*3+e2)*3+e3 — write transposed (e0 innermost)
    if (tid < 162) {
        int pack = tid & 1, i = tid >> 1;
        int e3 = i % 3, e2 = (i / 3) % 3, e1 = (i / 9) % 3, e0 = i / 27;
        int outi = ((e3 * 3 + e2) * 3 + e1) * 3 + e0;
        ((u64*)g_C)[outi * 2 + pack] = bufA[i * 2 + pack];
    }
}

// ---------------- Kernel B: main batched pass ----------------
__global__ void __launch_bounds__(TPB, 4)
quantum_kernel(const float* __restrict__ x,
               const float* __restrict__ W,
               const float* __restrict__ b,
               const float* __restrict__ gamma,
               const float* __restrict__ beta,
               float* __restrict__ out, int Bn)
{
    __shared__ __align__(16) ulonglong2 sC[81];
    __shared__ __align__(16) u64 sWC[32][8];            // per-lane phase-2 constants
    __shared__ float sK[32];                            // LN constants
    __shared__ __align__(16) u64 s_q2[WARPS][32][4];
    __shared__ __align__(16) u64 s_m2[WARPS][32][2];

    const int tid  = threadIdx.x;
    const int lane = tid & 31;
    const int wid  = tid >> 5;

    if (tid < 162) ((u64*)sC)[tid] = ((const u64*)g_C)[tid];
    if (tid < 32) {
        sK[tid] = g_consts[tid];
        const int j0 = 2 * tid;
        float4 w0 = *(const float4*)(W + j0 * 4);
        float4 w1 = *(const float4*)(W + j0 * 4 + 4);
        sWC[tid][0] = pk(w0.x, w1.x);
        sWC[tid][1] = pk(w0.y, w1.y);
        sWC[tid][2] = pk(w0.z, w1.z);
        sWC[tid][3] = pk(w0.w, w1.w);
        sWC[tid][4] = pk(b[j0],     b[j0 + 1]);
        sWC[tid][5] = pk(gamma[j0], gamma[j0 + 1]);
        sWC[tid][6] = pk(beta[j0],  beta[j0 + 1]);
    }
    __syncthreads();

    const int warp_global = blockIdx.x * WARPS + wid;
    const int nwarps  = GRID * WARPS;
    const int nchunks = Bn >> 5;
    const int j0 = 2 * lane;

    for (int chunk = warp_global; chunk < nchunks; chunk += nwarps) {
        const int base = chunk << 5;
        const int s = base + lane;

        // ---- phase 1: one sample per lane ----
        float4 xv = *(const float4*)(x + (size_t)s * 4);
        float xs[4] = {xv.x, xv.y, xv.z, xv.w};
        u64 cp[4], sp[4];
        #pragma unroll
        for (int w = 0; w < 4; w++) {
            float t  = __expf(xs[w] + xs[w]);
            float th = 1.f - __fdividef(2.f, t + 1.f);        // tanh
            float ang = 3.14159265358979323846f * th;         // theta
            float sn, cs;
            __sincosf(ang, &sn, &cs);
            cp[w] = pk(cs, cs);
            sp[w] = pk(sn, sn);
        }

        // z = sum_e C[e] * prod_w (1, cos, sin)_{e_w}
        u64 z01 = 0ull, z23 = 0ull;
        #pragma unroll
        for (int e3 = 0; e3 < 3; e3++) {
            u64 a3_01, a3_23;
            #pragma unroll
            for (int e2 = 0; e2 < 3; e2++) {
                u64 a2_01, a2_23;
                #pragma unroll
                for (int e1 = 0; e1 < 3; e1++) {
                    int cbase = ((e3 * 3 + e2) * 3 + e1) * 3;
                    ulonglong2 C0 = sC[cbase];
                    ulonglong2 C1 = sC[cbase + 1];
                    ulonglong2 C2 = sC[cbase + 2];
                    u64 t01 = fma2(cp[0], C1.x, C0.x); t01 = fma2(sp[0], C2.x, t01);
                    u64 t23 = fma2(cp[0], C1.y, C0.y); t23 = fma2(sp[0], C2.y, t23);
                    if (e1 == 0)      { a2_01 = t01;                   a2_23 = t23; }
                    else if (e1 == 1) { a2_01 = fma2(cp[1], t01, a2_01); a2_23 = fma2(cp[1], t23, a2_23); }
                    else              { a2_01 = fma2(sp[1], t01, a2_01); a2_23 = fma2(sp[1], t23, a2_23); }
                }
                if (e2 == 0)      { a3_01 = a2_01;                    a3_23 = a2_23; }
                else if (e2 == 1) { a3_01 = fma2(cp[2], a2_01, a3_01); a3_23 = fma2(cp[2], a2_23, a3_23); }
                else              { a3_01 = fma2(sp[2], a2_01, a3_01); a3_23 = fma2(sp[2], a2_23, a3_23); }
            }
            if (e3 == 0)      { z01 = a3_01;                    z23 = a3_23; }
            else if (e3 == 1) { z01 = fma2(cp[3], a3_01, z01);  z23 = fma2(cp[3], a3_23, z23); }
            else              { z01 = fma2(sp[3], a3_01, z01);  z23 = fma2(sp[3], a3_23, z23); }
        }
        float2 zA = upk(z01), zB = upk(z23);
        float z0 = zA.x, z1 = zA.y, z2 = zB.x, z3 = zB.y;

        // softmax
        float m = fmaxf(fmaxf(z0, z1), fmaxf(z2, z3));
        float q0 = __expf(z0 - m), q1 = __expf(z1 - m), q2 = __expf(z2 - m), q3 = __expf(z3 - m);
        float inv = __fdividef(1.f, (q0 + q1) + (q2 + q3));
        q0 *= inv; q1 *= inv; q2 *= inv; q3 *= inv;
        float qa[4] = {q0, q1, q2, q3};

        // LN stats via precomputed quadratic forms
        float mu = sK[25];
        #pragma unroll
        for (int i = 0; i < 4; i++) mu = fmaf(sK[21 + i], qa[i], mu);
        float eh2 = sK[20];
        #pragma unroll
        for (int i = 0; i < 4; i++) {
            float ti = 2.f * sK[16 + i];
            #pragma unroll
            for (int jj = 0; jj < 4; jj++) ti = fmaf(sK[i * 4 + jj], qa[jj], ti);
            eh2 = fmaf(qa[i], ti, eh2);
        }
        float var = eh2 - mu * mu;
        float rs = rsqrtf(var + 1e-5f);

        s_q2[wid][lane][0] = pk(q0, q0);
        s_q2[wid][lane][1] = pk(q1, q1);
        s_q2[wid][lane][2] = pk(q2, q2);
        s_q2[wid][lane][3] = pk(q3, q3);
        s_m2[wid][lane][0] = pk(-mu, -mu);
        s_m2[wid][lane][1] = pk(rs, rs);
        __syncwarp();

        // ---- phase 2: warp-transposed, coalesced 256B row stores ----
        const u64* wc = sWC[lane];
        u64 Wp0 = wc[0], Wp1 = wc[1], Wp2 = wc[2], Wp3 = wc[3];
        u64 bp = wc[4], gp = wc[5], betap = wc[6];
        float* orow = out + (size_t)base * PROJ + j0;
        #pragma unroll 8
        for (int s2 = 0; s2 < 32; s2++) {
            const ulonglong2* qp = (const ulonglong2*)&s_q2[wid][s2][0];
            ulonglong2 qA = qp[0], qB = qp[1];
            const ulonglong2* mp = (const ulonglong2*)&s_m2[wid][s2][0];
            ulonglong2 mm = mp[0];
            u64 h = fma2(Wp0, qA.x, bp);
            h = fma2(Wp1, qA.y, h);
            h = fma2(Wp2, qB.x, h);
            h = fma2(Wp3, qB.y, h);
            u64 rg = mul2(gp, mm.y);
            u64 d  = fma2(mm.x, rg, betap);
            u64 ov = fma2(h, rg, d);
            *(float2*)(orow + (size_t)s2 * PROJ) = upk(ov);
        }
        __syncwarp();
    }
}

extern "C" void kernel_launch(void* const* d_in, const int* in_sizes, int n_in,
                              void* d_out, int out_size)
{
    const float* x       = (const float*)d_in[0];
    const float* weights = (const float*)d_in[1];
    const float* W       = (const float*)d_in[2];
    const float* b       = (const float*)d_in[3];
    const float* gamma   = (const float*)d_in[4];
    const float* beta    = (const float*)d_in[5];
    float* out = (float*)d_out;
    int Bn = in_sizes[0] / NQ;

    precompute_kernel<<<1, 256>>>(weights, W, b);
    quantum_kernel<<<GRID, TPB>>>(x, W, b, gamma, beta, out, Bn);
}

// round 4
// speedup vs baseline: 1.5140x; 1.5140x over previous
#include <cuda_runtime.h>
#include <cstdint>

typedef unsigned long long u64;

#define NQ   4
#define PROJ 64
#define TPB  256
#define WARPS (TPB/32)
#define GRID 444

// ---------------- f32x2 helpers (Blackwell packed fp32) ----------------
__device__ __forceinline__ u64 pk(float lo, float hi) {
    u64 r; asm("mov.b64 %0, {%1, %2};" : "=l"(r) : "f"(lo), "f"(hi)); return r;
}
__device__ __forceinline__ float2 upk(u64 v) {
    float2 r; asm("mov.b64 {%0, %1}, %2;" : "=f"(r.x), "=f"(r.y) : "l"(v)); return r;
}
__device__ __forceinline__ u64 fma2(u64 a, u64 b, u64 c) {
    u64 d; asm("fma.rn.f32x2 %0, %1, %2, %3;" : "=l"(d) : "l"(a), "l"(b), "l"(c)); return d;
}
__device__ __forceinline__ u64 mul2(u64 a, u64 b) {
    u64 d; asm("mul.rn.f32x2 %0, %1, %2;" : "=l"(d) : "l"(a), "l"(b)); return d;
}

// ---------------- device-global precomputed tables ----------------
// g_C[idx] for idx = ((e3*3+e2)*3+e1)*3+e0 : .x = (z0,z1) coeff, .y = (z2,z3) coeff
__device__ ulonglong2 g_C[81];
// 0..15: A = W^T W / 64, 16..19: u = W^T b / 64, 20: e=|b|^2/64,
// 21..24: wbar = colmean(W), 25: bbar = mean(b)
__device__ float g_consts[32];

// ---------------- Kernel A: build coefficient tensor and LN constants ----------------
__global__ void precompute_kernel(const float* __restrict__ weights,
                                  const float* __restrict__ W,
                                  const float* __restrict__ b)
{
    __shared__ float2 sM[8][4];
    __shared__ float sVr[16][16];   // [o][j]
    __shared__ float sVi[16][16];
    __shared__ u64 bufA[512];
    __shared__ u64 bufB[384];

    int tid = threadIdx.x;

    if (tid < 8) {
        int l = tid >> 2, w = tid & 3;
        float phi = weights[l * 12 + w * 3 + 0];
        float th  = weights[l * 12 + w * 3 + 1];
        float om  = weights[l * 12 + w * 3 + 2];
        float c, s; sincosf(0.5f * th, &s, &c);
        float ap = -0.5f * (phi + om);
        float am =  0.5f * (phi - om);
        float cap, sap, cam, sam;
        sincosf(ap, &sap, &cap);
        sincosf(am, &sam, &cam);
        sM[tid][0] = make_float2( c * cap,  c * sap);
        sM[tid][1] = make_float2(-s * cam, -s * sam);
        sM[tid][2] = make_float2( s * cam, -s * sam);
        sM[tid][3] = make_float2( c * cap, -c * sap);
    }
    __syncthreads();

    // V columns (16 threads) — V = U_ent * diag((-i)^popcount)
    if (tid < 16) {
        const int j = tid;
        float ar[16], ai[16];
        #pragma unroll
        for (int o = 0; o < 16; o++) { ar[o] = (o == j) ? 1.f : 0.f; ai[o] = 0.f; }
        #pragma unroll
        for (int l = 0; l < 2; l++) {
            #pragma unroll
            for (int w = 0; w < NQ; w++) {
                int g = l * 4 + w;
                float2 M00 = sM[g][0], M01 = sM[g][1], M10 = sM[g][2], M11 = sM[g][3];
                int mask = 8 >> w;
                #pragma unroll
                for (int k = 0; k < 16; k++) if (!(k & mask)) {
                    int k1 = k | mask;
                    float a0r = ar[k],  a0i = ai[k];
                    float a1r = ar[k1], a1i = ai[k1];
                    ar[k]  = M00.x*a0r - M00.y*a0i + M01.x*a1r - M01.y*a1i;
                    ai[k]  = M00.x*a0i + M00.y*a0r + M01.x*a1i + M01.y*a1r;
                    ar[k1] = M10.x*a0r - M10.y*a0i + M11.x*a1r - M11.y*a1i;
                    ai[k1] = M10.x*a0i + M10.y*a0r + M11.x*a1i + M11.y*a1r;
                }
            }
            int rr = (l % 3) + 1;
            #pragma unroll
            for (int w = 0; w < NQ; w++) {
                int cm = 8 >> w, tm = 8 >> ((w + rr) & 3);
                #pragma unroll
                for (int k = 0; k < 16; k++) if ((k & cm) && !(k & tm)) {
                    int k1 = k | tm;
                    float tr = ar[k], ti = ai[k];
                    ar[k] = ar[k1];  ai[k] = ai[k1];
                    ar[k1] = tr;     ai[k1] = ti;
                }
            }
        }
        int pc = __popc(j) & 3;
        float fr = (pc == 0) ? 1.f : ((pc == 2) ? -1.f : 0.f);
        float fi = (pc == 1) ? -1.f : ((pc == 3) ? 1.f : 0.f);
        #pragma unroll
        for (int o = 0; o < 16; o++) {
            sVr[o][j] = ar[o] * fr - ai[o] * fi;
            sVi[o][j] = ar[o] * fi + ai[o] * fr;
        }
    }

    // warp 1: projection / LN constants (independent of V)
    if (tid >= 32 && tid < 64) {
        int lane = tid - 32;
        float A[16], u4[4], wb[4], e = 0.f, bb = 0.f;
        #pragma unroll
        for (int i = 0; i < 16; i++) A[i] = 0.f;
        #pragma unroll
        for (int i = 0; i < 4; i++) { u4[i] = 0.f; wb[i] = 0.f; }
        #pragma unroll
        for (int rep = 0; rep < 2; rep++) {
            int r = lane + rep * 32;
            float4 wr = *(const float4*)(W + r * 4);
            float br = b[r];
            float wv[4] = {wr.x, wr.y, wr.z, wr.w};
            #pragma unroll
            for (int i = 0; i < 4; i++) {
                #pragma unroll
                for (int jj = 0; jj < 4; jj++) A[i * 4 + jj] += wv[i] * wv[jj];
                u4[i] += wv[i] * br;
                wb[i] += wv[i];
            }
            e += br * br; bb += br;
        }
        #pragma unroll
        for (int off = 16; off > 0; off >>= 1) {
            #pragma unroll
            for (int i = 0; i < 16; i++) A[i] += __shfl_xor_sync(0xffffffffu, A[i], off);
            #pragma unroll
            for (int i = 0; i < 4; i++) {
                u4[i] += __shfl_xor_sync(0xffffffffu, u4[i], off);
                wb[i] += __shfl_xor_sync(0xffffffffu, wb[i], off);
            }
            e  += __shfl_xor_sync(0xffffffffu, e, off);
            bb += __shfl_xor_sync(0xffffffffu, bb, off);
        }
        if (lane == 0) {
            const float inv = 1.f / 64.f;
            #pragma unroll
            for (int i = 0; i < 16; i++) g_consts[i] = A[i] * inv;
            #pragma unroll
            for (int i = 0; i < 4; i++) {
                g_consts[16 + i] = u4[i] * inv;
                g_consts[21 + i] = wb[i] * inv;
            }
            g_consts[20] = e * inv;
            g_consts[25] = bb * inv;
        }
    }
    __syncthreads();

    // S_w[j][k] = sum_o sign_w(o) (VR[o][j]VR[o][k] + VI[o][j]VI[o][k]),
    // scattered into pair-radix layout: p_w = 2*bit_w(j) + bit_w(k)
    {
        int j = tid >> 4, k = tid & 15;
        float a0 = 0.f, a1 = 0.f, a2 = 0.f, a3 = 0.f;
        #pragma unroll
        for (int o = 0; o < 16; o++) {
            float d = sVr[o][j] * sVr[o][k] + sVi[o][j] * sVi[o][k];
            a0 += (o & 8) ? -d : d;
            a1 += (o & 4) ? -d : d;
            a2 += (o & 2) ? -d : d;
            a3 += (o & 1) ? -d : d;
        }
        int p0 = 2 * ((j >> 3) & 1) + ((k >> 3) & 1);
        int p1 = 2 * ((j >> 2) & 1) + ((k >> 2) & 1);
        int p2 = 2 * ((j >> 1) & 1) + ((k >> 1) & 1);
        int p3 = 2 * (j & 1) + (k & 1);
        int idx = ((p0 * 4 + p1) * 4 + p2) * 4 + p3;
        bufA[idx * 2 + 0] = pk(a0, a1);
        bufA[idx * 2 + 1] = pk(a2, a3);
    }
    __syncthreads();

    // 4 per-wire contractions: pair index (radix 4) -> (1,cos,sin) basis (radix 3)
    {
        const int pow3[4] = {1, 3, 9, 27};
        const int P4s[4]  = {64, 16, 4, 1};
        for (int s = 0; s < 4; s++) {
            u64* In  = (s & 1) ? bufB : bufA;
            u64* Out = (s & 1) ? bufA : bufB;
            int P4 = P4s[s];
            int nitems = pow3[s] * P4 * 2;
            if (tid < nitems) {
                int pack = tid & 1, i = tid >> 1;
                int E = i / P4, P = i % P4;
                float2 v0 = upk(In[((E * 4 + 0) * P4 + P) * 2 + pack]);
                float2 v1 = upk(In[((E * 4 + 1) * P4 + P) * 2 + pack]);
                float2 v2 = upk(In[((E * 4 + 2) * P4 + P) * 2 + pack]);
                float2 v3 = upk(In[((E * 4 + 3) * P4 + P) * 2 + pack]);
                Out[((E * 3 + 0) * P4 + P) * 2 + pack] = pk(0.5f*(v0.x+v3.x), 0.5f*(v0.y+v3.y));
                Out[((E * 3 + 1) * P4 + P) * 2 + pack] = pk(0.5f*(v0.x-v3.x), 0.5f*(v0.y-v3.y));
                Out[((E * 3 + 2) * P4 + P) * 2 + pack] = pk(0.5f*(v1.x+v2.x), 0.5f*(v1.y+v2.y));
            }
            __syncthreads();
        }
    }
    // result in bufA, layout ((e0*3+e1)*3+e2)*3+e3 — write transposed (e0 innermost)
    if (tid < 162) {
        int pack = tid & 1, i = tid >> 1;
        int e3 = i % 3, e2 = (i / 3) % 3, e1 = (i / 9) % 3, e0 = i / 27;
        int outi = ((e3 * 3 + e2) * 3 + e1) * 3 + e0;
        ((u64*)g_C)[outi * 2 + pack] = bufA[i * 2 + pack];
    }
}

// ---------------- Kernel B: main batched pass ----------------
__global__ void __launch_bounds__(TPB, 3)
quantum_kernel(const float* __restrict__ x,
               const float* __restrict__ W,
               const float* __restrict__ b,
               const float* __restrict__ gamma,
               const float* __restrict__ beta,
               float* __restrict__ out, int Bn)
{
    __shared__ __align__(16) ulonglong2 sC[81];
    __shared__ __align__(16) u64 sWC[32][8];            // per-lane phase-2 constants
    __shared__ float sK[32];                            // LN constants
    __shared__ __align__(16) u64 s_q2[WARPS][32][4];    // q*rs packed {v,v}
    __shared__ __align__(16) u64 s_m2[WARPS][32][2];    // {rs,rs}, {-mu*rs,-mu*rs}

    const int tid  = threadIdx.x;
    const int lane = tid & 31;
    const int wid  = tid >> 5;

    if (tid < 162) ((u64*)sC)[tid] = ((const u64*)g_C)[tid];
    if (tid < 32) {
        sK[tid] = g_consts[tid];
        const int j0 = 2 * tid;
        float4 w0 = *(const float4*)(W + j0 * 4);
        float4 w1 = *(const float4*)(W + j0 * 4 + 4);
        sWC[tid][0] = pk(w0.x, w1.x);
        sWC[tid][1] = pk(w0.y, w1.y);
        sWC[tid][2] = pk(w0.z, w1.z);
        sWC[tid][3] = pk(w0.w, w1.w);
        sWC[tid][4] = pk(b[j0],     b[j0 + 1]);
        sWC[tid][5] = pk(gamma[j0], gamma[j0 + 1]);
        sWC[tid][6] = pk(beta[j0],  beta[j0 + 1]);
    }
    __syncthreads();

    const int warp_global = blockIdx.x * WARPS + wid;
    const int nwarps  = GRID * WARPS;
    const int nchunks = Bn >> 5;
    const int j0 = 2 * lane;

    for (int chunk = warp_global; chunk < nchunks; chunk += nwarps) {
        const int base = chunk << 5;
        const int s = base + lane;

        // ---- phase 1: one sample per lane ----
        float4 xv = *(const float4*)(x + (size_t)s * 4);
        float xs[4] = {xv.x, xv.y, xv.z, xv.w};
        u64 cp[4], sp[4];
        #pragma unroll
        for (int w = 0; w < 4; w++) {
            float t  = __expf(xs[w] + xs[w]);
            float th = 1.f - __fdividef(2.f, t + 1.f);        // tanh
            float ang = 3.14159265358979323846f * th;         // theta
            float sn, cs;
            __sincosf(ang, &sn, &cs);
            cp[w] = pk(cs, cs);
            sp[w] = pk(sn, sn);
        }

        // z = sum_e C[e] * prod_w (1, cos, sin)_{e_w}
        u64 z01 = 0ull, z23 = 0ull;
        #pragma unroll
        for (int e3 = 0; e3 < 3; e3++) {
            u64 a3_01, a3_23;
            #pragma unroll
            for (int e2 = 0; e2 < 3; e2++) {
                u64 a2_01, a2_23;
                #pragma unroll
                for (int e1 = 0; e1 < 3; e1++) {
                    int cbase = ((e3 * 3 + e2) * 3 + e1) * 3;
                    ulonglong2 C0 = sC[cbase];
                    ulonglong2 C1 = sC[cbase + 1];
                    ulonglong2 C2 = sC[cbase + 2];
                    u64 t01 = fma2(cp[0], C1.x, C0.x); t01 = fma2(sp[0], C2.x, t01);
                    u64 t23 = fma2(cp[0], C1.y, C0.y); t23 = fma2(sp[0], C2.y, t23);
                    if (e1 == 0)      { a2_01 = t01;                   a2_23 = t23; }
                    else if (e1 == 1) { a2_01 = fma2(cp[1], t01, a2_01); a2_23 = fma2(cp[1], t23, a2_23); }
                    else              { a2_01 = fma2(sp[1], t01, a2_01); a2_23 = fma2(sp[1], t23, a2_23); }
                }
                if (e2 == 0)      { a3_01 = a2_01;                    a3_23 = a2_23; }
                else if (e2 == 1) { a3_01 = fma2(cp[2], a2_01, a3_01); a3_23 = fma2(cp[2], a2_23, a3_23); }
                else              { a3_01 = fma2(sp[2], a2_01, a3_01); a3_23 = fma2(sp[2], a2_23, a3_23); }
            }
            if (e3 == 0)      { z01 = a3_01;                    z23 = a3_23; }
            else if (e3 == 1) { z01 = fma2(cp[3], a3_01, z01);  z23 = fma2(cp[3], a3_23, z23); }
            else              { z01 = fma2(sp[3], a3_01, z01);  z23 = fma2(sp[3], a3_23, z23); }
        }
        float2 zA = upk(z01), zB = upk(z23);

        // softmax — z values are expvals in [-1,1], no max-shift needed
        float q0 = __expf(zA.x), q1 = __expf(zA.y), q2 = __expf(zB.x), q3 = __expf(zB.y);
        float inv = __fdividef(1.f, (q0 + q1) + (q2 + q3));
        q0 *= inv; q1 *= inv; q2 *= inv; q3 *= inv;
        float qa[4] = {q0, q1, q2, q3};

        // LN stats via precomputed quadratic forms
        float mu = sK[25];
        #pragma unroll
        for (int i = 0; i < 4; i++) mu = fmaf(sK[21 + i], qa[i], mu);
        float eh2 = sK[20];
        #pragma unroll
        for (int i = 0; i < 4; i++) {
            float ti = 2.f * sK[16 + i];
            #pragma unroll
            for (int jj = 0; jj < 4; jj++) ti = fmaf(sK[i * 4 + jj], qa[jj], ti);
            eh2 = fmaf(qa[i], ti, eh2);
        }
        float var = eh2 - mu * mu;
        float rs = rsqrtf(var + 1e-5f);

        // store rs-scaled q so phase 2 needs one fewer op per sample
        float q0r = q0 * rs, q1r = q1 * rs, q2r = q2 * rs, q3r = q3 * rs;
        float nmr = -mu * rs;
        s_q2[wid][lane][0] = pk(q0r, q0r);
        s_q2[wid][lane][1] = pk(q1r, q1r);
        s_q2[wid][lane][2] = pk(q2r, q2r);
        s_q2[wid][lane][3] = pk(q3r, q3r);
        s_m2[wid][lane][0] = pk(rs, rs);
        s_m2[wid][lane][1] = pk(nmr, nmr);
        __syncwarp();

        // ---- phase 2: warp-transposed, coalesced 256B row stores ----
        const u64* wc = sWC[lane];
        u64 Wp0 = wc[0], Wp1 = wc[1], Wp2 = wc[2], Wp3 = wc[3];
        u64 bp = wc[4], gp = wc[5], betap = wc[6];
        float* orow = out + (size_t)base * PROJ + j0;
        #pragma unroll 8
        for (int s2 = 0; s2 < 32; s2++) {
            const ulonglong2* qp = (const ulonglong2*)&s_q2[wid][s2][0];
            ulonglong2 qA = qp[0], qB = qp[1];
            const ulonglong2* mp = (const ulonglong2*)&s_m2[wid][s2][0];
            ulonglong2 mm = mp[0];
            // acc = b*rs - mu*rs + W·(q*rs);  out = gamma*acc + beta
            u64 acc = fma2(bp, mm.x, mm.y);
            acc = fma2(Wp0, qA.x, acc);
            acc = fma2(Wp1, qA.y, acc);
            acc = fma2(Wp2, qB.x, acc);
            acc = fma2(Wp3, qB.y, acc);
            u64 ov = fma2(gp, acc, betap);
            *(float2*)(orow + (size_t)s2 * PROJ) = upk(ov);
        }
        __syncwarp();
    }
}

extern "C" void kernel_launch(void* const* d_in, const int* in_sizes, int n_in,
                              void* d_out, int out_size)
{
    const float* x       = (const float*)d_in[0];
    const float* weights = (const float*)d_in[1];
    const float* W       = (const float*)d_in[2];
    const float* b       = (const float*)d_in[3];
    const float* gamma   = (const float*)d_in[4];
    const float* beta    = (const float*)d_in[5];
    float* out = (float*)d_out;
    int Bn = in_sizes[0] / NQ;

    precompute_kernel<<<1, 256>>>(weights, W, b);
    quantum_kernel<<<GRID, TPB>>>(x, W, b, gamma, beta, out, Bn);
}

// round 5
// speedup vs baseline: 1.7802x; 1.1758x over previous
#include <cuda_runtime.h>
#include <cstdint>

typedef unsigned long long u64;

#define NQ   4
#define PROJ 64
#define TPB  256
#define WARPS (TPB/32)
#define GRID 296

// ---------------- f32x2 helpers (Blackwell packed fp32) ----------------
__device__ __forceinline__ u64 pk(float lo, float hi) {
    u64 r; asm("mov.b64 %0, {%1, %2};" : "=l"(r) : "f"(lo), "f"(hi)); return r;
}
__device__ __forceinline__ float2 upk(u64 v) {
    float2 r; asm("mov.b64 {%0, %1}, %2;" : "=f"(r.x), "=f"(r.y) : "l"(v)); return r;
}
__device__ __forceinline__ u64 fma2(u64 a, u64 b, u64 c) {
    u64 d; asm("fma.rn.f32x2 %0, %1, %2, %3;" : "=l"(d) : "l"(a), "l"(b), "l"(c)); return d;
}
__device__ __forceinline__ u64 mul2(u64 a, u64 b) {
    u64 d; asm("mul.rn.f32x2 %0, %1, %2;" : "=l"(d) : "l"(a), "l"(b)); return d;
}

// ---------------- device-global precomputed tables ----------------
// g_C[idx] for idx = ((e3*3+e2)*3+e1)*3+e0 : .x = (z0,z1) coeff, .y = (z2,z3) coeff
__device__ ulonglong2 g_C[81];
// 0..15: A = W^T W / 64, 16..19: u = W^T b / 64, 20: e=|b|^2/64,
// 21..24: wbar = colmean(W), 25: bbar = mean(b)
__device__ float g_consts[32];
// packed LN constants {v,v}; indices 16..19 hold {2u,2u}
__device__ u64 g_K2[26];
// G[i][pair] = {gamma_j*(W[j][i]-wbar_i+b_j-bbar)} for j=2*pair, 2*pair+1
__device__ u64 g_G[4 * 32];
__device__ u64 g_beta2[32];

// ---------------- Kernel A: build tables ----------------
__global__ void precompute_kernel(const float* __restrict__ weights,
                                  const float* __restrict__ W,
                                  const float* __restrict__ b,
                                  const float* __restrict__ gamma,
                                  const float* __restrict__ beta)
{
    __shared__ float2 sM[8][4];
    __shared__ float sVr[16][16];   // [o][j]
    __shared__ float sVi[16][16];
    __shared__ u64 bufA[512];
    __shared__ u64 bufB[384];

    int tid = threadIdx.x;

    if (tid < 8) {
        int l = tid >> 2, w = tid & 3;
        float phi = weights[l * 12 + w * 3 + 0];
        float th  = weights[l * 12 + w * 3 + 1];
        float om  = weights[l * 12 + w * 3 + 2];
        float c, s; sincosf(0.5f * th, &s, &c);
        float ap = -0.5f * (phi + om);
        float am =  0.5f * (phi - om);
        float cap, sap, cam, sam;
        sincosf(ap, &sap, &cap);
        sincosf(am, &sam, &cam);
        sM[tid][0] = make_float2( c * cap,  c * sap);
        sM[tid][1] = make_float2(-s * cam, -s * sam);
        sM[tid][2] = make_float2( s * cam, -s * sam);
        sM[tid][3] = make_float2( c * cap, -c * sap);
    }
    __syncthreads();

    // V columns (16 threads) — V = U_ent * diag((-i)^popcount)
    if (tid < 16) {
        const int j = tid;
        float ar[16], ai[16];
        #pragma unroll
        for (int o = 0; o < 16; o++) { ar[o] = (o == j) ? 1.f : 0.f; ai[o] = 0.f; }
        #pragma unroll
        for (int l = 0; l < 2; l++) {
            #pragma unroll
            for (int w = 0; w < NQ; w++) {
                int g = l * 4 + w;
                float2 M00 = sM[g][0], M01 = sM[g][1], M10 = sM[g][2], M11 = sM[g][3];
                int mask = 8 >> w;
                #pragma unroll
                for (int k = 0; k < 16; k++) if (!(k & mask)) {
                    int k1 = k | mask;
                    float a0r = ar[k],  a0i = ai[k];
                    float a1r = ar[k1], a1i = ai[k1];
                    ar[k]  = M00.x*a0r - M00.y*a0i + M01.x*a1r - M01.y*a1i;
                    ai[k]  = M00.x*a0i + M00.y*a0r + M01.x*a1i + M01.y*a1r;
                    ar[k1] = M10.x*a0r - M10.y*a0i + M11.x*a1r - M11.y*a1i;
                    ai[k1] = M10.x*a0i + M10.y*a0r + M11.x*a1i + M11.y*a1r;
                }
            }
            int rr = (l % 3) + 1;
            #pragma unroll
            for (int w = 0; w < NQ; w++) {
                int cm = 8 >> w, tm = 8 >> ((w + rr) & 3);
                #pragma unroll
                for (int k = 0; k < 16; k++) if ((k & cm) && !(k & tm)) {
                    int k1 = k | tm;
                    float tr = ar[k], ti = ai[k];
                    ar[k] = ar[k1];  ai[k] = ai[k1];
                    ar[k1] = tr;     ai[k1] = ti;
                }
            }
        }
        int pc = __popc(j) & 3;
        float fr = (pc == 0) ? 1.f : ((pc == 2) ? -1.f : 0.f);
        float fi = (pc == 1) ? -1.f : ((pc == 3) ? 1.f : 0.f);
        #pragma unroll
        for (int o = 0; o < 16; o++) {
            sVr[o][j] = ar[o] * fr - ai[o] * fi;
            sVi[o][j] = ar[o] * fi + ai[o] * fr;
        }
    }

    // warp 1: projection / LN constants
    if (tid >= 32 && tid < 64) {
        int lane = tid - 32;
        float A[16], u4[4], wb[4], e = 0.f, bb = 0.f;
        #pragma unroll
        for (int i = 0; i < 16; i++) A[i] = 0.f;
        #pragma unroll
        for (int i = 0; i < 4; i++) { u4[i] = 0.f; wb[i] = 0.f; }
        #pragma unroll
        for (int rep = 0; rep < 2; rep++) {
            int r = lane + rep * 32;
            float4 wr = *(const float4*)(W + r * 4);
            float br = b[r];
            float wv[4] = {wr.x, wr.y, wr.z, wr.w};
            #pragma unroll
            for (int i = 0; i < 4; i++) {
                #pragma unroll
                for (int jj = 0; jj < 4; jj++) A[i * 4 + jj] += wv[i] * wv[jj];
                u4[i] += wv[i] * br;
                wb[i] += wv[i];
            }
            e += br * br; bb += br;
        }
        #pragma unroll
        for (int off = 16; off > 0; off >>= 1) {
            #pragma unroll
            for (int i = 0; i < 16; i++) A[i] += __shfl_xor_sync(0xffffffffu, A[i], off);
            #pragma unroll
            for (int i = 0; i < 4; i++) {
                u4[i] += __shfl_xor_sync(0xffffffffu, u4[i], off);
                wb[i] += __shfl_xor_sync(0xffffffffu, wb[i], off);
            }
            e  += __shfl_xor_sync(0xffffffffu, e, off);
            bb += __shfl_xor_sync(0xffffffffu, bb, off);
        }
        if (lane == 0) {
            const float inv = 1.f / 64.f;
            #pragma unroll
            for (int i = 0; i < 16; i++) g_consts[i] = A[i] * inv;
            #pragma unroll
            for (int i = 0; i < 4; i++) {
                g_consts[16 + i] = u4[i] * inv;
                g_consts[21 + i] = wb[i] * inv;
            }
            g_consts[20] = e * inv;
            g_consts[25] = bb * inv;
        }
    }
    __syncthreads();

    // S_w[j][k] -> pair-radix layout
    {
        int j = tid >> 4, k = tid & 15;
        float a0 = 0.f, a1 = 0.f, a2 = 0.f, a3 = 0.f;
        #pragma unroll
        for (int o = 0; o < 16; o++) {
            float d = sVr[o][j] * sVr[o][k] + sVi[o][j] * sVi[o][k];
            a0 += (o & 8) ? -d : d;
            a1 += (o & 4) ? -d : d;
            a2 += (o & 2) ? -d : d;
            a3 += (o & 1) ? -d : d;
        }
        int p0 = 2 * ((j >> 3) & 1) + ((k >> 3) & 1);
        int p1 = 2 * ((j >> 2) & 1) + ((k >> 2) & 1);
        int p2 = 2 * ((j >> 1) & 1) + ((k >> 1) & 1);
        int p3 = 2 * (j & 1) + (k & 1);
        int idx = ((p0 * 4 + p1) * 4 + p2) * 4 + p3;
        bufA[idx * 2 + 0] = pk(a0, a1);
        bufA[idx * 2 + 1] = pk(a2, a3);
    }
    __syncthreads();

    // 4 per-wire contractions: radix-4 pair -> radix-3 (1,cos,sin)
    {
        const int pow3[4] = {1, 3, 9, 27};
        const int P4s[4]  = {64, 16, 4, 1};
        for (int s = 0; s < 4; s++) {
            u64* In  = (s & 1) ? bufB : bufA;
            u64* Out = (s & 1) ? bufA : bufB;
            int P4 = P4s[s];
            int nitems = pow3[s] * P4 * 2;
            if (tid < nitems) {
                int pack = tid & 1, i = tid >> 1;
                int E = i / P4, P = i % P4;
                float2 v0 = upk(In[((E * 4 + 0) * P4 + P) * 2 + pack]);
                float2 v1 = upk(In[((E * 4 + 1) * P4 + P) * 2 + pack]);
                float2 v2 = upk(In[((E * 4 + 2) * P4 + P) * 2 + pack]);
                float2 v3 = upk(In[((E * 4 + 3) * P4 + P) * 2 + pack]);
                Out[((E * 3 + 0) * P4 + P) * 2 + pack] = pk(0.5f*(v0.x+v3.x), 0.5f*(v0.y+v3.y));
                Out[((E * 3 + 1) * P4 + P) * 2 + pack] = pk(0.5f*(v0.x-v3.x), 0.5f*(v0.y-v3.y));
                Out[((E * 3 + 2) * P4 + P) * 2 + pack] = pk(0.5f*(v1.x+v2.x), 0.5f*(v1.y+v2.y));
            }
            __syncthreads();
        }
    }
    // transpose-write g_C (e0 innermost)
    if (tid < 162) {
        int pack = tid & 1, i = tid >> 1;
        int e3 = i % 3, e2 = (i / 3) % 3, e1 = (i / 9) % 3, e0 = i / 27;
        int outi = ((e3 * 3 + e2) * 3 + e1) * 3 + e0;
        ((u64*)g_C)[outi * 2 + pack] = bufA[i * 2 + pack];
    }
    // folded projection table G, beta pairs  (g_consts visible since pre-sync)
    if (tid >= 192 && tid < 224) {
        int lane = tid - 192;
        int j0 = 2 * lane, j1 = j0 + 1;
        float b0 = b[j0], b1 = b[j1];
        float g0 = gamma[j0], g1 = gamma[j1];
        float bb = g_consts[25];
        #pragma unroll
        for (int i = 0; i < 4; i++) {
            float wb = g_consts[21 + i];
            float w0 = W[j0 * 4 + i] - wb + b0 - bb;
            float w1 = W[j1 * 4 + i] - wb + b1 - bb;
            g_G[i * 32 + lane] = pk(g0 * w0, g1 * w1);
        }
        g_beta2[lane] = pk(beta[j0], beta[j1]);
    }
    // replicated LN constants, with u doubled
    if (tid >= 224 && tid < 250) {
        int i = tid - 224;
        float v = g_consts[i];
        if (i >= 16 && i < 20) v = 2.f * v;
        g_K2[i] = pk(v, v);
    }
}

// ---------------- Kernel B: main batched pass ----------------
__global__ void __launch_bounds__(TPB, 2)
quantum_kernel(const float* __restrict__ x,
               float* __restrict__ out, int Bn)
{
    __shared__ __align__(16) ulonglong2 sC[81];
    __shared__ __align__(16) u64 sK2[26];
    __shared__ __align__(16) u64 s_q[WARPS][2][32][4];   // q*rs packed {v,v}

    const int tid  = threadIdx.x;
    const int lane = tid & 31;
    const int wid  = tid >> 5;

    if (tid < 162) ((u64*)sC)[tid] = ((const u64*)g_C)[tid];
    if (tid < 26)  sK2[tid] = g_K2[tid];
    __syncthreads();

    // per-lane folded projection constants (registers for whole kernel)
    u64 G0 = g_G[0 * 32 + lane];
    u64 G1 = g_G[1 * 32 + lane];
    u64 G2 = g_G[2 * 32 + lane];
    u64 G3 = g_G[3 * 32 + lane];
    u64 betap = g_beta2[lane];

    const int warp_global = blockIdx.x * WARPS + wid;
    const int nwarps  = GRID * WARPS;
    const int nchunks = Bn >> 6;              // 64 samples per chunk
    const int j0 = 2 * lane;

    for (int chunk = warp_global; chunk < nchunks; chunk += nwarps) {
        const int base = chunk << 6;
        const int sA = base + lane;
        const int sB = sA + 32;

        // ---- phase 1: two samples per lane ----
        float4 xA = *(const float4*)(x + (size_t)sA * 4);
        float4 xB = *(const float4*)(x + (size_t)sB * 4);
        float xsA[4] = {xA.x, xA.y, xA.z, xA.w};
        float xsB[4] = {xB.x, xB.y, xB.z, xB.w};
        u64 cpA[4], spA[4], cpB[4], spB[4];
        #pragma unroll
        for (int w = 0; w < 4; w++) {
            float tA  = __expf(xsA[w] + xsA[w]);
            float thA = 1.f - __fdividef(2.f, tA + 1.f);
            float snA, csA;
            __sincosf(3.14159265358979323846f * thA, &snA, &csA);
            cpA[w] = pk(csA, csA); spA[w] = pk(snA, snA);
            float tB  = __expf(xsB[w] + xsB[w]);
            float thB = 1.f - __fdividef(2.f, tB + 1.f);
            float snB, csB;
            __sincosf(3.14159265358979323846f * thB, &snB, &csB);
            cpB[w] = pk(csB, csB); spB[w] = pk(snB, snB);
        }

        // z = sum_e C[e] * prod_w (1,cos,sin)_{e_w}  — both samples share C loads
        u64 zA01 = 0ull, zA23 = 0ull, zB01 = 0ull, zB23 = 0ull;
        #pragma unroll
        for (int e3 = 0; e3 < 3; e3++) {
            u64 a3A01, a3A23, a3B01, a3B23;
            #pragma unroll
            for (int e2 = 0; e2 < 3; e2++) {
                u64 a2A01, a2A23, a2B01, a2B23;
                #pragma unroll
                for (int e1 = 0; e1 < 3; e1++) {
                    int cbase = ((e3 * 3 + e2) * 3 + e1) * 3;
                    ulonglong2 C0 = sC[cbase];
                    ulonglong2 C1 = sC[cbase + 1];
                    ulonglong2 C2 = sC[cbase + 2];
                    u64 tA01 = fma2(cpA[0], C1.x, C0.x); tA01 = fma2(spA[0], C2.x, tA01);
                    u64 tA23 = fma2(cpA[0], C1.y, C0.y); tA23 = fma2(spA[0], C2.y, tA23);
                    u64 tB01 = fma2(cpB[0], C1.x, C0.x); tB01 = fma2(spB[0], C2.x, tB01);
                    u64 tB23 = fma2(cpB[0], C1.y, C0.y); tB23 = fma2(spB[0], C2.y, tB23);
                    if (e1 == 0) {
                        a2A01 = tA01; a2A23 = tA23; a2B01 = tB01; a2B23 = tB23;
                    } else if (e1 == 1) {
                        a2A01 = fma2(cpA[1], tA01, a2A01); a2A23 = fma2(cpA[1], tA23, a2A23);
                        a2B01 = fma2(cpB[1], tB01, a2B01); a2B23 = fma2(cpB[1], tB23, a2B23);
                    } else {
                        a2A01 = fma2(spA[1], tA01, a2A01); a2A23 = fma2(spA[1], tA23, a2A23);
                        a2B01 = fma2(spB[1], tB01, a2B01); a2B23 = fma2(spB[1], tB23, a2B23);
                    }
                }
                if (e2 == 0) {
                    a3A01 = a2A01; a3A23 = a2A23; a3B01 = a2B01; a3B23 = a2B23;
                } else if (e2 == 1) {
                    a3A01 = fma2(cpA[2], a2A01, a3A01); a3A23 = fma2(cpA[2], a2A23, a3A23);
                    a3B01 = fma2(cpB[2], a2B01, a3B01); a3B23 = fma2(cpB[2], a2B23, a3B23);
                } else {
                    a3A01 = fma2(spA[2], a2A01, a3A01); a3A23 = fma2(spA[2], a2A23, a3A23);
                    a3B01 = fma2(spB[2], a2B01, a3B01); a3B23 = fma2(spB[2], a2B23, a3B23);
                }
            }
            if (e3 == 0) {
                zA01 = a3A01; zA23 = a3A23; zB01 = a3B01; zB23 = a3B23;
            } else if (e3 == 1) {
                zA01 = fma2(cpA[3], a3A01, zA01); zA23 = fma2(cpA[3], a3A23, zA23);
                zB01 = fma2(cpB[3], a3B01, zB01); zB23 = fma2(cpB[3], a3B23, zB23);
            } else {
                zA01 = fma2(spA[3], a3A01, zA01); zA23 = fma2(spA[3], a3A23, zA23);
                zB01 = fma2(spB[3], a3B01, zB01); zB23 = fma2(spB[3], a3B23, zB23);
            }
        }
        float2 zAa = upk(zA01), zAb = upk(zA23);
        float2 zBa = upk(zB01), zBb = upk(zB23);

        // softmax (z in [-1,1], no max-shift needed)
        float qA0 = __expf(zAa.x), qA1 = __expf(zAa.y), qA2 = __expf(zAb.x), qA3 = __expf(zAb.y);
        float invA = __fdividef(1.f, (qA0 + qA1) + (qA2 + qA3));
        qA0 *= invA; qA1 *= invA; qA2 *= invA; qA3 *= invA;
        float qB0 = __expf(zBa.x), qB1 = __expf(zBa.y), qB2 = __expf(zBb.x), qB3 = __expf(zBb.y);
        float invB = __fdividef(1.f, (qB0 + qB1) + (qB2 + qB3));
        qB0 *= invB; qB1 *= invB; qB2 *= invB; qB3 *= invB;

        // LN variance via quadratic forms, packed across the two samples
        u64 q2[4];
        q2[0] = pk(qA0, qB0); q2[1] = pk(qA1, qB1);
        q2[2] = pk(qA2, qB2); q2[3] = pk(qA3, qB3);
        u64 mu2 = sK2[25];
        #pragma unroll
        for (int i = 0; i < 4; i++) mu2 = fma2(sK2[21 + i], q2[i], mu2);
        u64 eh2 = sK2[20];
        #pragma unroll
        for (int i = 0; i < 4; i++) {
            u64 ti = sK2[16 + i];                 // {2u_i,2u_i}
            #pragma unroll
            for (int jj = 0; jj < 4; jj++) ti = fma2(sK2[i * 4 + jj], q2[jj], ti);
            eh2 = fma2(q2[i], ti, eh2);
        }
        float2 E = upk(eh2), M = upk(mu2);
        float rsA = rsqrtf(fmaf(-M.x, M.x, E.x) + 1e-5f);
        float rsB = rsqrtf(fmaf(-M.y, M.y, E.y) + 1e-5f);

        // store rs-scaled q per sample, replicated {v,v} for phase 2
        {
            float a0 = qA0 * rsA, a1 = qA1 * rsA, a2 = qA2 * rsA, a3 = qA3 * rsA;
            ulonglong2* dst = (ulonglong2*)&s_q[wid][0][lane][0];
            dst[0] = make_ulonglong2(pk(a0, a0), pk(a1, a1));
            dst[1] = make_ulonglong2(pk(a2, a2), pk(a3, a3));
            float b0 = qB0 * rsB, b1 = qB1 * rsB, b2 = qB2 * rsB, b3 = qB3 * rsB;
            ulonglong2* dst2 = (ulonglong2*)&s_q[wid][1][lane][0];
            dst2[0] = make_ulonglong2(pk(b0, b0), pk(b1, b1));
            dst2[1] = make_ulonglong2(pk(b2, b2), pk(b3, b3));
        }
        __syncwarp();

        // ---- phase 2: warp-transposed, coalesced 256B row stores ----
        #pragma unroll
        for (int g = 0; g < 2; g++) {
            float* orow = out + (size_t)(base + g * 32) * PROJ + j0;
            #pragma unroll 8
            for (int s2 = 0; s2 < 32; s2++) {
                const ulonglong2* qp = (const ulonglong2*)&s_q[wid][g][s2][0];
                ulonglong2 qa = qp[0], qb = qp[1];
                u64 acc = fma2(G0, qa.x, betap);
                acc = fma2(G1, qa.y, acc);
                acc = fma2(G2, qb.x, acc);
                acc = fma2(G3, qb.y, acc);
                *(float2*)(orow + (size_t)s2 * PROJ) = upk(acc);
            }
        }
        __syncwarp();
    }
}

extern "C" void kernel_launch(void* const* d_in, const int* in_sizes, int n_in,
                              void* d_out, int out_size)
{
    const float* x       = (const float*)d_in[0];
    const float* weights = (const float*)d_in[1];
    const float* W       = (const float*)d_in[2];
    const float* b       = (const float*)d_in[3];
    const float* gamma   = (const float*)d_in[4];
    const float* beta    = (const float*)d_in[5];
    float* out = (float*)d_out;
    int Bn = in_sizes[0] / NQ;

    precompute_kernel<<<1, 256>>>(weights, W, b, gamma, beta);
    quantum_kernel<<<GRID, TPB>>>(x, out, Bn);
}

// round 6
// speedup vs baseline: 1.8025x; 1.0125x over previous
#include <cuda_runtime.h>
#include <cstdint>

typedef unsigned long long u64;

#define NQ   4
#define PROJ 64
#define TPB  256
#define WARPS (TPB/32)
#define GRID 444

// ---------------- f32x2 helpers (Blackwell packed fp32) ----------------
__device__ __forceinline__ u64 pk(float lo, float hi) {
    u64 r; asm("mov.b64 %0, {%1, %2};" : "=l"(r) : "f"(lo), "f"(hi)); return r;
}
__device__ __forceinline__ float2 upk(u64 v) {
    float2 r; asm("mov.b64 {%0, %1}, %2;" : "=f"(r.x), "=f"(r.y) : "l"(v)); return r;
}
__device__ __forceinline__ u64 fma2(u64 a, u64 b, u64 c) {
    u64 d; asm("fma.rn.f32x2 %0, %1, %2, %3;" : "=l"(d) : "l"(a), "l"(b), "l"(c)); return d;
}

// ---------------- device-global precomputed tables ----------------
// g_C[idx] for idx = ((e3*3+e2)*3+e1)*3+e0 : .x = (z0,z1) coeff, .y = (z2,z3) coeff
__device__ ulonglong2 g_C[81];
// 0..15: A = W^T W / 64, 16..19: u = W^T b / 64, 20: e=|b|^2/64,
// 21..24: wbar = colmean(W), 25: bbar = mean(b)
__device__ float g_consts[32];
// scalar LN constants with u pre-doubled at 16..19
__device__ float g_Ks[26];
// folded projection, 4-col groups: g_G4[(i*16+g)*2 + h] = {gamma_j*(W[j][i]-wbar_i+b_j-bbar)}
// for j = 4g+2h, 4g+2h+1
__device__ u64 g_G4[4 * 16 * 2];
__device__ u64 g_beta4[16 * 2];

// ---------------- Kernel A: build tables ----------------
__global__ void precompute_kernel(const float* __restrict__ weights,
                                  const float* __restrict__ W,
                                  const float* __restrict__ b,
                                  const float* __restrict__ gamma,
                                  const float* __restrict__ beta)
{
    __shared__ float2 sM[8][4];
    __shared__ float sVr[16][16];   // [o][j]
    __shared__ float sVi[16][16];
    __shared__ u64 bufA[512];
    __shared__ u64 bufB[384];

    int tid = threadIdx.x;

    if (tid < 8) {
        int l = tid >> 2, w = tid & 3;
        float phi = weights[l * 12 + w * 3 + 0];
        float th  = weights[l * 12 + w * 3 + 1];
        float om  = weights[l * 12 + w * 3 + 2];
        float c, s; sincosf(0.5f * th, &s, &c);
        float ap = -0.5f * (phi + om);
        float am =  0.5f * (phi - om);
        float cap, sap, cam, sam;
        sincosf(ap, &sap, &cap);
        sincosf(am, &sam, &cam);
        sM[tid][0] = make_float2( c * cap,  c * sap);
        sM[tid][1] = make_float2(-s * cam, -s * sam);
        sM[tid][2] = make_float2( s * cam, -s * sam);
        sM[tid][3] = make_float2( c * cap, -c * sap);
    }
    __syncthreads();

    // V columns (16 threads) — V = U_ent * diag((-i)^popcount)
    if (tid < 16) {
        const int j = tid;
        float ar[16], ai[16];
        #pragma unroll
        for (int o = 0; o < 16; o++) { ar[o] = (o == j) ? 1.f : 0.f; ai[o] = 0.f; }
        #pragma unroll
        for (int l = 0; l < 2; l++) {
            #pragma unroll
            for (int w = 0; w < NQ; w++) {
                int g = l * 4 + w;
                float2 M00 = sM[g][0], M01 = sM[g][1], M10 = sM[g][2], M11 = sM[g][3];
                int mask = 8 >> w;
                #pragma unroll
                for (int k = 0; k < 16; k++) if (!(k & mask)) {
                    int k1 = k | mask;
                    float a0r = ar[k],  a0i = ai[k];
                    float a1r = ar[k1], a1i = ai[k1];
                    ar[k]  = M00.x*a0r - M00.y*a0i + M01.x*a1r - M01.y*a1i;
                    ai[k]  = M00.x*a0i + M00.y*a0r + M01.x*a1i + M01.y*a1r;
                    ar[k1] = M10.x*a0r - M10.y*a0i + M11.x*a1r - M11.y*a1i;
                    ai[k1] = M10.x*a0i + M10.y*a0r + M11.x*a1i + M11.y*a1r;
                }
            }
            int rr = (l % 3) + 1;
            #pragma unroll
            for (int w = 0; w < NQ; w++) {
                int cm = 8 >> w, tm = 8 >> ((w + rr) & 3);
                #pragma unroll
                for (int k = 0; k < 16; k++) if ((k & cm) && !(k & tm)) {
                    int k1 = k | tm;
                    float tr = ar[k], ti = ai[k];
                    ar[k] = ar[k1];  ai[k] = ai[k1];
                    ar[k1] = tr;     ai[k1] = ti;
                }
            }
        }
        int pc = __popc(j) & 3;
        float fr = (pc == 0) ? 1.f : ((pc == 2) ? -1.f : 0.f);
        float fi = (pc == 1) ? -1.f : ((pc == 3) ? 1.f : 0.f);
        #pragma unroll
        for (int o = 0; o < 16; o++) {
            sVr[o][j] = ar[o] * fr - ai[o] * fi;
            sVi[o][j] = ar[o] * fi + ai[o] * fr;
        }
    }

    // warp 1: projection / LN constants
    if (tid >= 32 && tid < 64) {
        int lane = tid - 32;
        float A[16], u4[4], wb[4], e = 0.f, bb = 0.f;
        #pragma unroll
        for (int i = 0; i < 16; i++) A[i] = 0.f;
        #pragma unroll
        for (int i = 0; i < 4; i++) { u4[i] = 0.f; wb[i] = 0.f; }
        #pragma unroll
        for (int rep = 0; rep < 2; rep++) {
            int r = lane + rep * 32;
            float4 wr = *(const float4*)(W + r * 4);
            float br = b[r];
            float wv[4] = {wr.x, wr.y, wr.z, wr.w};
            #pragma unroll
            for (int i = 0; i < 4; i++) {
                #pragma unroll
                for (int jj = 0; jj < 4; jj++) A[i * 4 + jj] += wv[i] * wv[jj];
                u4[i] += wv[i] * br;
                wb[i] += wv[i];
            }
            e += br * br; bb += br;
        }
        #pragma unroll
        for (int off = 16; off > 0; off >>= 1) {
            #pragma unroll
            for (int i = 0; i < 16; i++) A[i] += __shfl_xor_sync(0xffffffffu, A[i], off);
            #pragma unroll
            for (int i = 0; i < 4; i++) {
                u4[i] += __shfl_xor_sync(0xffffffffu, u4[i], off);
                wb[i] += __shfl_xor_sync(0xffffffffu, wb[i], off);
            }
            e  += __shfl_xor_sync(0xffffffffu, e, off);
            bb += __shfl_xor_sync(0xffffffffu, bb, off);
        }
        if (lane == 0) {
            const float inv = 1.f / 64.f;
            #pragma unroll
            for (int i = 0; i < 16; i++) g_consts[i] = A[i] * inv;
            #pragma unroll
            for (int i = 0; i < 4; i++) {
                g_consts[16 + i] = u4[i] * inv;
                g_consts[21 + i] = wb[i] * inv;
            }
            g_consts[20] = e * inv;
            g_consts[25] = bb * inv;
        }
    }
    __syncthreads();

    // S_w[j][k] -> pair-radix layout
    {
        int j = tid >> 4, k = tid & 15;
        float a0 = 0.f, a1 = 0.f, a2 = 0.f, a3 = 0.f;
        #pragma unroll
        for (int o = 0; o < 16; o++) {
            float d = sVr[o][j] * sVr[o][k] + sVi[o][j] * sVi[o][k];
            a0 += (o & 8) ? -d : d;
            a1 += (o & 4) ? -d : d;
            a2 += (o & 2) ? -d : d;
            a3 += (o & 1) ? -d : d;
        }
        int p0 = 2 * ((j >> 3) & 1) + ((k >> 3) & 1);
        int p1 = 2 * ((j >> 2) & 1) + ((k >> 2) & 1);
        int p2 = 2 * ((j >> 1) & 1) + ((k >> 1) & 1);
        int p3 = 2 * (j & 1) + (k & 1);
        int idx = ((p0 * 4 + p1) * 4 + p2) * 4 + p3;
        bufA[idx * 2 + 0] = pk(a0, a1);
        bufA[idx * 2 + 1] = pk(a2, a3);
    }
    __syncthreads();

    // 4 per-wire contractions: radix-4 pair -> radix-3 (1,cos,sin)
    {
        const int pow3[4] = {1, 3, 9, 27};
        const int P4s[4]  = {64, 16, 4, 1};
        for (int s = 0; s < 4; s++) {
            u64* In  = (s & 1) ? bufB : bufA;
            u64* Out = (s & 1) ? bufA : bufB;
            int P4 = P4s[s];
            int nitems = pow3[s] * P4 * 2;
            if (tid < nitems) {
                int pack = tid & 1, i = tid >> 1;
                int E = i / P4, P = i % P4;
                float2 v0 = upk(In[((E * 4 + 0) * P4 + P) * 2 + pack]);
                float2 v1 = upk(In[((E * 4 + 1) * P4 + P) * 2 + pack]);
                float2 v2 = upk(In[((E * 4 + 2) * P4 + P) * 2 + pack]);
                float2 v3 = upk(In[((E * 4 + 3) * P4 + P) * 2 + pack]);
                Out[((E * 3 + 0) * P4 + P) * 2 + pack] = pk(0.5f*(v0.x+v3.x), 0.5f*(v0.y+v3.y));
                Out[((E * 3 + 1) * P4 + P) * 2 + pack] = pk(0.5f*(v0.x-v3.x), 0.5f*(v0.y-v3.y));
                Out[((E * 3 + 2) * P4 + P) * 2 + pack] = pk(0.5f*(v1.x+v2.x), 0.5f*(v1.y+v2.y));
            }
            __syncthreads();
        }
    }
    // transpose-write g_C (e0 innermost)
    if (tid < 162) {
        int pack = tid & 1, i = tid >> 1;
        int e3 = i % 3, e2 = (i / 3) % 3, e1 = (i / 9) % 3, e0 = i / 27;
        int outi = ((e3 * 3 + e2) * 3 + e1) * 3 + e0;
        ((u64*)g_C)[outi * 2 + pack] = bufA[i * 2 + pack];
    }
    // folded projection table, 4-col groups
    if (tid >= 192 && tid < 208) {
        int g = tid - 192;
        float bb = g_consts[25];
        #pragma unroll
        for (int h = 0; h < 2; h++) {
            int j0 = 4 * g + 2 * h, j1 = j0 + 1;
            float b0 = b[j0], b1 = b[j1];
            float g0 = gamma[j0], g1 = gamma[j1];
            #pragma unroll
            for (int i = 0; i < 4; i++) {
                float wb = g_consts[21 + i];
                float w0 = W[j0 * 4 + i] - wb + b0 - bb;
                float w1 = W[j1 * 4 + i] - wb + b1 - bb;
                g_G4[(i * 16 + g) * 2 + h] = pk(g0 * w0, g1 * w1);
            }
            g_beta4[g * 2 + h] = pk(beta[j0], beta[j1]);
        }
    }
    // scalar LN constants (u doubled)
    if (tid >= 224 && tid < 250) {
        int i = tid - 224;
        float v = g_consts[i];
        if (i >= 16 && i < 20) v = 2.f * v;
        g_Ks[i] = v;
    }
}

// ---------------- Kernel B: main batched pass ----------------
__global__ void __launch_bounds__(TPB, 3)
quantum_kernel(const float* __restrict__ x,
               float* __restrict__ out, int Bn)
{
    __shared__ __align__(16) ulonglong2 sC[81];
    __shared__ float sK[26];
    __shared__ __align__(16) u64 s_q[WARPS][32][4];   // q*rs packed {v,v}

    const int tid  = threadIdx.x;
    const int lane = tid & 31;
    const int wid  = tid >> 5;

    if (tid < 162) ((u64*)sC)[tid] = ((const u64*)g_C)[tid];
    if (tid < 26)  sK[tid] = g_Ks[tid];
    __syncthreads();

    // per-lane folded projection constants: 4 output columns j = 4*g4 .. 4*g4+3
    const int g4 = lane & 15;
    const int p  = lane >> 4;
    u64 Glo[4], Ghi[4];
    #pragma unroll
    for (int i = 0; i < 4; i++) {
        Glo[i] = g_G4[(i * 16 + g4) * 2 + 0];
        Ghi[i] = g_G4[(i * 16 + g4) * 2 + 1];
    }
    u64 beta_lo = g_beta4[g4 * 2 + 0];
    u64 beta_hi = g_beta4[g4 * 2 + 1];

    const int warp_global = blockIdx.x * WARPS + wid;
    const int nwarps  = GRID * WARPS;
    const int nchunks = Bn >> 5;              // 32 samples per chunk
    const int jcol = 4 * g4;

    for (int chunk = warp_global; chunk < nchunks; chunk += nwarps) {
        const int base = chunk << 5;
        const int s = base + lane;

        // ---- phase 1: one sample per lane ----
        float4 xv = *(const float4*)(x + (size_t)s * 4);
        float xs[4] = {xv.x, xv.y, xv.z, xv.w};
        u64 cp[4], sp[4];
        #pragma unroll
        for (int w = 0; w < 4; w++) {
            float t  = __expf(xs[w] + xs[w]);
            float th = 1.f - __fdividef(2.f, t + 1.f);        // tanh
            float sn, cs;
            __sincosf(3.14159265358979323846f * th, &sn, &cs);
            cp[w] = pk(cs, cs);
            sp[w] = pk(sn, sn);
        }

        // z = sum_e C[e] * prod_w (1,cos,sin)_{e_w}
        u64 z01 = 0ull, z23 = 0ull;
        #pragma unroll
        for (int e3 = 0; e3 < 3; e3++) {
            u64 a3_01, a3_23;
            #pragma unroll
            for (int e2 = 0; e2 < 3; e2++) {
                u64 a2_01, a2_23;
                #pragma unroll
                for (int e1 = 0; e1 < 3; e1++) {
                    int cbase = ((e3 * 3 + e2) * 3 + e1) * 3;
                    ulonglong2 C0 = sC[cbase];
                    ulonglong2 C1 = sC[cbase + 1];
                    ulonglong2 C2 = sC[cbase + 2];
                    u64 t01 = fma2(cp[0], C1.x, C0.x); t01 = fma2(sp[0], C2.x, t01);
                    u64 t23 = fma2(cp[0], C1.y, C0.y); t23 = fma2(sp[0], C2.y, t23);
                    if (e1 == 0)      { a2_01 = t01;                   a2_23 = t23; }
                    else if (e1 == 1) { a2_01 = fma2(cp[1], t01, a2_01); a2_23 = fma2(cp[1], t23, a2_23); }
                    else              { a2_01 = fma2(sp[1], t01, a2_01); a2_23 = fma2(sp[1], t23, a2_23); }
                }
                if (e2 == 0)      { a3_01 = a2_01;                    a3_23 = a2_23; }
                else if (e2 == 1) { a3_01 = fma2(cp[2], a2_01, a3_01); a3_23 = fma2(cp[2], a2_23, a3_23); }
                else              { a3_01 = fma2(sp[2], a2_01, a3_01); a3_23 = fma2(sp[2], a2_23, a3_23); }
            }
            if (e3 == 0)      { z01 = a3_01;                    z23 = a3_23; }
            else if (e3 == 1) { z01 = fma2(cp[3], a3_01, z01);  z23 = fma2(cp[3], a3_23, z23); }
            else              { z01 = fma2(sp[3], a3_01, z01);  z23 = fma2(sp[3], a3_23, z23); }
        }
        float2 zA = upk(z01), zB = upk(z23);

        // softmax (z in [-1,1], no max-shift needed)
        float q0 = __expf(zA.x), q1 = __expf(zA.y), q2 = __expf(zB.x), q3 = __expf(zB.y);
        float inv = __fdividef(1.f, (q0 + q1) + (q2 + q3));
        q0 *= inv; q1 *= inv; q2 *= inv; q3 *= inv;
        float qa[4] = {q0, q1, q2, q3};

        // LN stats via precomputed quadratic forms (scalar)
        float mu = sK[25];
        #pragma unroll
        for (int i = 0; i < 4; i++) mu = fmaf(sK[21 + i], qa[i], mu);
        float eh2 = sK[20];
        #pragma unroll
        for (int i = 0; i < 4; i++) {
            float ti = sK[16 + i];                // 2u_i (pre-doubled)
            #pragma unroll
            for (int jj = 0; jj < 4; jj++) ti = fmaf(sK[i * 4 + jj], qa[jj], ti);
            eh2 = fmaf(qa[i], ti, eh2);
        }
        float var = fmaf(-mu, mu, eh2);
        float rs = rsqrtf(var + 1e-5f);

        // store rs-scaled q, replicated {v,v}
        {
            float a0 = q0 * rs, a1 = q1 * rs, a2 = q2 * rs, a3 = q3 * rs;
            ulonglong2* dst = (ulonglong2*)&s_q[wid][lane][0];
            dst[0] = make_ulonglong2(pk(a0, a0), pk(a1, a1));
            dst[1] = make_ulonglong2(pk(a2, a2), pk(a3, a3));
        }
        __syncwarp();

        // ---- phase 2: half-warp per row, 4 cols/lane, STG.128 ----
        #pragma unroll 4
        for (int r = 0; r < 16; r++) {
            const int row = 2 * r + p;
            const ulonglong2* qp = (const ulonglong2*)&s_q[wid][row][0];
            ulonglong2 qa2 = qp[0], qb2 = qp[1];
            u64 acc_lo = fma2(Glo[0], qa2.x, beta_lo);
            u64 acc_hi = fma2(Ghi[0], qa2.x, beta_hi);
            acc_lo = fma2(Glo[1], qa2.y, acc_lo);
            acc_hi = fma2(Ghi[1], qa2.y, acc_hi);
            acc_lo = fma2(Glo[2], qb2.x, acc_lo);
            acc_hi = fma2(Ghi[2], qb2.x, acc_hi);
            acc_lo = fma2(Glo[3], qb2.y, acc_lo);
            acc_hi = fma2(Ghi[3], qb2.y, acc_hi);
            float2 lo = upk(acc_lo), hi = upk(acc_hi);
            float4 ov = make_float4(lo.x, lo.y, hi.x, hi.y);
            *(float4*)(out + (size_t)(base + row) * PROJ + jcol) = ov;
        }
        __syncwarp();
    }
}

extern "C" void kernel_launch(void* const* d_in, const int* in_sizes, int n_in,
                              void* d_out, int out_size)
{
    const float* x       = (const float*)d_in[0];
    const float* weights = (const float*)d_in[1];
    const float* W       = (const float*)d_in[2];
    const float* b       = (const float*)d_in[3];
    const float* gamma   = (const float*)d_in[4];
    const float* beta    = (const float*)d_in[5];
    float* out = (float*)d_out;
    int Bn = in_sizes[0] / NQ;

    precompute_kernel<<<1, 256>>>(weights, W, b, gamma, beta);
    quantum_kernel<<<GRID, TPB>>>(x, out, Bn);
}